// round 4
// baseline (speedup 1.0000x reference)
#include <cuda_runtime.h>
#include <math.h>

#define SEQ 8192
#define E   384
#define H   192
#define G4  768
#define T   11
#define STARTTAG 9
#define STOPTAG  10
#define NEGV (-10000.0f)
#define CSZ 8   // cluster size per direction

// ---------------- device scratch (static: allowed) ----------------
__device__ float d_gpre[2][SEQ][G4];   // input-projected gates + bias
__device__ float d_h[2][SEQ][H];       // hf, hb
__device__ float d_feats[SEQ][T];

// ---------------- helpers ----------------
__device__ __forceinline__ unsigned smem_u32(const void* p) {
    unsigned a;
    asm("{ .reg .u64 t; cvta.to.shared.u64 t, %1; cvt.u32.u64 %0, t; }"
        : "=r"(a) : "l"(p));
    return a;
}
__device__ __forceinline__ float sigmoidf_(float x) {
    return __fdividef(1.0f, 1.0f + __expf(-x));
}
__device__ __forceinline__ float tanhf_(float x) {
    float ax = fabsf(x);
    float e  = __expf(2.0f * ax);
    float r  = 1.0f - __fdividef(2.0f, e + 1.0f);
    return copysignf(r, x);
}
__device__ __forceinline__ unsigned long long mx64(unsigned long long a,
                                                   unsigned long long b) {
    return a > b ? a : b;
}
// cluster-scope acquire wait on local mbarrier, phase-parity spin
__device__ __forceinline__ void mbar_wait_cluster(unsigned addr, unsigned parity) {
    asm volatile(
        "{\n\t.reg .pred P;\n"
        "W%=:\n\t"
        "mbarrier.try_wait.parity.acquire.cluster.shared::cta.b64 P, [%0], %1, 0x989680;\n\t"
        "@!P bra W%=;\n\t}"
        :: "r"(addr), "r"(parity) : "memory");
}

// =====================================================================
// Kernel 1: embedding gather + input projection GEMM (both directions)
// grid (256, 2), 256 threads. W loads vectorized float4 (4x fewer L1tex wf).
// =====================================================================
__global__ __launch_bounds__(256) void gemm_in_kernel(
    const int* __restrict__ sent, const float* __restrict__ emb,
    const float* __restrict__ w_f, const float* __restrict__ b1f, const float* __restrict__ b2f,
    const float* __restrict__ w_b, const float* __restrict__ b1b, const float* __restrict__ b2b)
{
    __shared__ float xs[E * 32];   // [k][r], 48 KB
    const int dir = blockIdx.y;
    const int t0  = blockIdx.x * 32;
    const int tid = threadIdx.x;
    const float* w   = dir ? w_b : w_f;
    const float* bb1 = dir ? b1b : b1f;
    const float* bb2 = dir ? b2b : b2f;

    #pragma unroll 1
    for (int i = 0; i < 48; i++) {
        int f = tid + i * 256;
        int r = f & 31, k = f >> 5;
        int tok = __ldg(sent + t0 + r);
        xs[k * 32 + r] = __ldg(emb + (size_t)tok * E + k);
    }
    __syncthreads();

    #pragma unroll 1
    for (int ch = 0; ch < 3; ch++) {
        int g = ch * 256 + tid;
        const float4* wr4 = (const float4*)(w + (size_t)g * E);
        float acc[32];
        #pragma unroll
        for (int r = 0; r < 32; r++) acc[r] = 0.0f;

        #pragma unroll 2
        for (int k4 = 0; k4 < E / 4; k4++) {
            float4 wv = __ldg(wr4 + k4);
            #pragma unroll
            for (int s = 0; s < 4; s++) {
                float wvs = (s == 0) ? wv.x : (s == 1) ? wv.y : (s == 2) ? wv.z : wv.w;
                const float4* x4 = (const float4*)(xs + (k4 * 4 + s) * 32);
                #pragma unroll
                for (int q = 0; q < 8; q++) {
                    float4 xv = x4[q];            // broadcast across warp
                    acc[4*q+0] += xv.x * wvs;
                    acc[4*q+1] += xv.y * wvs;
                    acc[4*q+2] += xv.z * wvs;
                    acc[4*q+3] += xv.w * wvs;
                }
            }
        }
        float bias = __ldg(bb1 + g) + __ldg(bb2 + g);
        #pragma unroll
        for (int r = 0; r < 32; r++)
            d_gpre[dir][t0 + r][g] = acc[r] + bias;
    }
}

// =====================================================================
// Kernel 2: LSTM scans. 2 clusters of 8 CTAs, 192 threads/CTA.
// W_hh slice register-resident. Per-step sync via parity mbarriers:
// producers DSMEM-store h + arrive.release on every CTA's mbarrier;
// consumers acquire-wait. No cluster barrier (no UCGABAR/CCTL.IVALL),
// mapa hoisted, single __syncthreads per step.
// =====================================================================
__global__ void __cluster_dims__(CSZ, 1, 1) __launch_bounds__(192, 1)
lstm_kernel(const float* __restrict__ whf, const float* __restrict__ whb)
{
    __shared__ __align__(16) float hbuf[2][H];
    __shared__ float part[192];
    __shared__ __align__(8) unsigned long long mb[2];

    unsigned rank; asm("mov.u32 %0, %%cluster_ctarank;" : "=r"(rank));
    const int dir = blockIdx.x >> 3;
    const int tid = threadIdx.x;
    const int gl  = tid % 96;          // local gate
    const int kh  = tid / 96;          // k half (0/1)
    const int typ = gl / 24, idx = gl % 24;
    const int gg  = typ * 192 + (int)rank * 24 + idx;   // global gate row
    const float* wh = dir ? whb : whf;

    // resident recurrent weights: 48 packed f32x2 per thread
    unsigned long long wreg[48];
    const unsigned long long* wrow =
        (const unsigned long long*)(wh + (size_t)gg * H) + kh * 48;
    #pragma unroll
    for (int j = 0; j < 48; j++) wreg[j] = __ldg(wrow + j);

    for (int i = tid; i < 2 * H; i += 192) (&hbuf[0][0])[i] = 0.0f;
    if (tid == 0) {
        unsigned m0 = smem_u32(&mb[0]);
        asm volatile("mbarrier.init.shared.b64 [%0], %1;" :: "r"(m0), "r"(24 * CSZ) : "memory");
        asm volatile("mbarrier.init.shared.b64 [%0], %1;" :: "r"(m0 + 8), "r"(24 * CSZ) : "memory");
    }
    float c = 0.0f;
    __syncthreads();
    // one cluster sync: all CTAs' mbarriers + zeroed hbufs visible
    asm volatile("barrier.cluster.arrive.aligned;" ::: "memory");
    asm volatile("barrier.cluster.wait.aligned;"   ::: "memory");

    const float* gp = &d_gpre[dir][0][0];
    float* hout = &d_h[dir][0][0];
    const int hidx = (int)rank * 24 + (tid < 24 ? tid : 0);

    // hoisted remote addresses (producers only use them)
    unsigned ra_h[2][CSZ], ra_mb[2][CSZ];
    {
        unsigned lh0 = smem_u32(&hbuf[0][hidx]);
        unsigned lh1 = smem_u32(&hbuf[1][hidx]);
        unsigned lm  = smem_u32(&mb[0]);
        #pragma unroll
        for (int r = 0; r < CSZ; r++) {
            asm("mapa.shared::cluster.u32 %0, %1, %2;" : "=r"(ra_h[0][r]) : "r"(lh0), "r"(r));
            asm("mapa.shared::cluster.u32 %0, %1, %2;" : "=r"(ra_h[1][r]) : "r"(lh1), "r"(r));
            asm("mapa.shared::cluster.u32 %0, %1, %2;" : "=r"(ra_mb[0][r]) : "r"(lm), "r"(r));
            asm("mapa.shared::cluster.u32 %0, %1, %2;" : "=r"(ra_mb[1][r]) : "r"(lm + 8), "r"(r));
        }
    }
    const unsigned mbl = smem_u32(&mb[0]);
    unsigned ph0 = 0, ph1 = 0;

    #pragma unroll 1
    for (int t = 0; t < SEQ; t++) {
        const int s = dir ? (SEQ - 1 - t) : t;
        const int b = t & 1;

        // prefetch this step's input-projected gates (producers: 4 each)
        float gp0 = 0.f, gp1 = 0.f, gp2 = 0.f, gp3 = 0.f;
        if (tid < 24) {
            const float* gpt = gp + (size_t)s * G4 + rank * 24 + tid;
            gp0 = __ldg(gpt);
            gp1 = __ldg(gpt + 192);
            gp2 = __ldg(gpt + 384);
            gp3 = __ldg(gpt + 576);
        }

        if (t > 0) {
            if (b) { mbar_wait_cluster(mbl + 8, ph1); ph1 ^= 1; }
            else   { mbar_wait_cluster(mbl,     ph0); ph0 ^= 1; }
        }

        // 96-MAC half-dot: LDS.128 h (warp-broadcast), f32x2 FMA, 2 accs
        const ulonglong2* h2 =
            (const ulonglong2*)((const char*)hbuf + b * (H * 4)) + kh * 24;
        unsigned long long acc0 = 0ull, acc1 = 0ull;
        #pragma unroll
        for (int j = 0; j < 24; j++) {
            ulonglong2 hv = h2[j];
            asm("fma.rn.f32x2 %0, %1, %2, %0;" : "+l"(acc0) : "l"(hv.x), "l"(wreg[2*j]));
            asm("fma.rn.f32x2 %0, %1, %2, %0;" : "+l"(acc1) : "l"(hv.y), "l"(wreg[2*j+1]));
        }
        float a0x, a0y, a1x, a1y;
        asm("mov.b64 {%0,%1}, %2;" : "=f"(a0x), "=f"(a0y) : "l"(acc0));
        asm("mov.b64 {%0,%1}, %2;" : "=f"(a1x), "=f"(a1y) : "l"(acc1));
        part[tid] = (a0x + a0y) + (a1x + a1y);
        __syncthreads();

        if (tid < 24) {
            float gi = part[tid]      + part[tid + 96]  + gp0;
            float gf = part[tid + 24] + part[tid + 120] + gp1;
            float gz = part[tid + 48] + part[tid + 144] + gp2;
            float go = part[tid + 72] + part[tid + 168] + gp3;
            float iv = sigmoidf_(gi);
            float fv = sigmoidf_(gf);
            float gv = tanhf_(gz);
            float ov = sigmoidf_(go);
            c = fv * c + iv * gv;
            float hv = ov * tanhf_(c);
            hout[(size_t)s * H + hidx] = hv;

            unsigned hb = __float_as_uint(hv);
            const int tp = b ^ 1;
            #pragma unroll
            for (int r = 0; r < CSZ; r++)
                asm volatile("st.shared::cluster.b32 [%0], %1;"
                             :: "r"(ra_h[tp][r]), "r"(hb) : "memory");
            #pragma unroll
            for (int r = 0; r < CSZ; r++)
                asm volatile("mbarrier.arrive.release.cluster.shared::cluster.b64 _, [%0];"
                             :: "r"(ra_mb[tp][r]) : "memory");
        }
    }

    // keep smem alive until all peers' last DSMEM ops land
    asm volatile("barrier.cluster.arrive.aligned;" ::: "memory");
    asm volatile("barrier.cluster.wait.aligned;"   ::: "memory");
}

// =====================================================================
// Kernel 3: feats[t][tag] = concat(hf,hb)[t] . w_tag[tag] + b_tag
// =====================================================================
__global__ __launch_bounds__(352) void feats_kernel(
    const float* __restrict__ wtag, const float* __restrict__ btag)
{
    __shared__ float ws[T * 2 * H];
    __shared__ float bs[T];
    const int tid = threadIdx.x;
    for (int i = tid; i < T * 2 * H; i += 352) ws[i] = __ldg(wtag + i);
    if (tid < T) bs[tid] = __ldg(btag + tid);
    __syncthreads();

    const int tl = tid / T, tag = tid % T;
    const int t = blockIdx.x * 32 + tl;
    float acc = bs[tag];
    const float* wr = ws + tag * (2 * H);
    #pragma unroll 4
    for (int k = 0; k < H; k++) acc += __ldg(&d_h[0][t][k]) * wr[k];
    #pragma unroll 4
    for (int k = 0; k < H; k++) acc += __ldg(&d_h[1][t][k]) * wr[H + k];
    d_feats[t][tag] = acc;
}

// =====================================================================
// Kernel 4: Viterbi. 1 warp. Packed u64 max-tree (breaks the 11-deep
// select chain; exact first-argmax tie-break), distance-2 feat prefetch,
// nibble-packed backpointers in 48 KB smem.
// =====================================================================
__global__ __launch_bounds__(32) void viterbi_kernel(
    const float* __restrict__ trans, float* __restrict__ out, int out_n)
{
    __shared__ unsigned char bsm[SEQ * 6];   // 49152 B
    const int lane = threadIdx.x;
    const int li = (lane < T) ? lane : 0;

    float tr[T];
    #pragma unroll
    for (int j = 0; j < T; j++) tr[j] = __ldg(trans + li * T + j);
    const float trStop = __ldg(trans + STOPTAG * T + li);

    float v = (lane == STARTTAG) ? 0.0f : NEGV;
    float fv0 = __ldg(&d_feats[0][li]);
    float fv1 = __ldg(&d_feats[1][li]);

    #pragma unroll 1
    for (int t = 0; t < SEQ; t++) {
        unsigned long long pk[T];
        #pragma unroll
        for (int j = 0; j < T; j++) {
            float vj = __shfl_sync(0xffffffffu, v, j);
            float sv = vj + tr[j];
            unsigned u = __float_as_uint(sv);
            unsigned key = u ^ ((((unsigned)((int)u >> 31)) >> 1) | 0x80000000u);
            pk[j] = ((unsigned long long)key << 4) | (unsigned)(10 - j);
        }
        unsigned long long a0 = mx64(pk[0], pk[1]);
        unsigned long long a1 = mx64(pk[2], pk[3]);
        unsigned long long a2 = mx64(pk[4], pk[5]);
        unsigned long long a3 = mx64(pk[6], pk[7]);
        unsigned long long a4 = mx64(pk[8], pk[9]);
        unsigned long long b0 = mx64(a0, a1);
        unsigned long long b1 = mx64(a2, a3);
        unsigned long long b2 = mx64(a4, pk[10]);
        unsigned long long best = mx64(mx64(b0, b1), b2);

        int bp = 10 - (int)(best & 15ull);
        unsigned key = (unsigned)(best >> 4);
        unsigned um = key ^ (((~((unsigned)((int)key >> 31))) >> 1) | 0x80000000u);
        float m = __uint_as_float(um);
        v = m + fv0;
        fv0 = fv1;
        int tn = t + 2 < SEQ ? t + 2 : SEQ - 1;
        fv1 = __ldg(&d_feats[tn][li]);

        int pb = __shfl_down_sync(0xffffffffu, bp, 1);
        if (lane < T && !(lane & 1)) {
            unsigned byte = (unsigned)bp | ((lane == 10 ? 0u : (unsigned)pb) << 4);
            bsm[t * 6 + (lane >> 1)] = (unsigned char)byte;
        }
    }

    float term = (lane < T) ? (v + trStop) : -3.4e38f;
    int bidx = lane;
    #pragma unroll
    for (int off = 16; off > 0; off >>= 1) {
        float ov = __shfl_down_sync(0xffffffffu, term, off);
        int   oi = __shfl_down_sync(0xffffffffu, bidx, off);
        if (ov > term || (ov == term && oi < bidx)) { term = ov; bidx = oi; }
    }
    if (lane == 0) {
        if (out_n > 0) out[0] = term;
        int cur = bidx;
        for (int t = SEQ - 1; t >= 0; t--) {
            if (1 + t < out_n) out[1 + t] = (float)cur;
            unsigned char byte = bsm[t * 6 + (cur >> 1)];
            cur = (cur & 1) ? (byte >> 4) : (byte & 15);
        }
    }
}

// =====================================================================
extern "C" void kernel_launch(void* const* d_in, const int* in_sizes, int n_in,
                              void* d_out, int out_size)
{
    const int*   sent   = (const int*)  d_in[0];
    const float* emb    = (const float*)d_in[1];
    const float* w_ih_f = (const float*)d_in[2];
    const float* w_hh_f = (const float*)d_in[3];
    const float* b_ih_f = (const float*)d_in[4];
    const float* b_hh_f = (const float*)d_in[5];
    const float* w_ih_b = (const float*)d_in[6];
    const float* w_hh_b = (const float*)d_in[7];
    const float* b_ih_b = (const float*)d_in[8];
    const float* b_hh_b = (const float*)d_in[9];
    const float* w_tag  = (const float*)d_in[10];
    const float* b_tag  = (const float*)d_in[11];
    const float* trans  = (const float*)d_in[12];
    float* out = (float*)d_out;

    gemm_in_kernel<<<dim3(SEQ / 32, 2), 256>>>(sent, emb,
        w_ih_f, b_ih_f, b_hh_f, w_ih_b, b_ih_b, b_hh_b);
    lstm_kernel<<<2 * CSZ, 192>>>(w_hh_f, w_hh_b);
    feats_kernel<<<SEQ / 32, 352>>>(w_tag, b_tag);
    viterbi_kernel<<<1, 32>>>(trans, out, out_size);
}

// round 5
// speedup vs baseline: 3.0387x; 3.0387x over previous
#include <cuda_runtime.h>
#include <math.h>

#define SEQ 8192
#define E   384
#define H   192
#define G4  768
#define T   11
#define STARTTAG 9
#define STOPTAG  10
#define NEGV (-10000.0f)
#define CSZ 8   // cluster size per direction

// ---------------- device scratch (static: allowed) ----------------
__device__ float d_gpre[2][SEQ][G4];   // input-projected gates + bias
__device__ float d_h[2][SEQ][H];       // hf, hb
__device__ float d_feats[SEQ][T];

// ---------------- helpers ----------------
__device__ __forceinline__ unsigned smem_u32(const void* p) {
    unsigned a;
    asm("{ .reg .u64 t; cvta.to.shared.u64 t, %1; cvt.u32.u64 %0, t; }"
        : "=r"(a) : "l"(p));
    return a;
}
__device__ __forceinline__ float sigmoidf_(float x) {
    return __fdividef(1.0f, 1.0f + __expf(-x));
}
__device__ __forceinline__ float tanhf_(float x) {
    float ax = fabsf(x);
    float e  = __expf(2.0f * ax);
    float r  = 1.0f - __fdividef(2.0f, e + 1.0f);
    return copysignf(r, x);
}
__device__ __forceinline__ unsigned long long mx64(unsigned long long a,
                                                   unsigned long long b) {
    return a > b ? a : b;
}
// cluster-scope acquire wait on local mbarrier, phase-parity spin
__device__ __forceinline__ void mbar_wait_cluster(unsigned addr, unsigned parity) {
    asm volatile(
        "{\n\t.reg .pred P;\n"
        "W%=:\n\t"
        "mbarrier.try_wait.parity.acquire.cluster.shared::cta.b64 P, [%0], %1, 0x989680;\n\t"
        "@!P bra W%=;\n\t}"
        :: "r"(addr), "r"(parity) : "memory");
}

// =====================================================================
// Kernel 1: embedding gather + input projection GEMM (both directions)
// grid (256, 2), 256 threads. W loads vectorized float4.
// =====================================================================
__global__ __launch_bounds__(256) void gemm_in_kernel(
    const int* __restrict__ sent, const float* __restrict__ emb,
    const float* __restrict__ w_f, const float* __restrict__ b1f, const float* __restrict__ b2f,
    const float* __restrict__ w_b, const float* __restrict__ b1b, const float* __restrict__ b2b)
{
    __shared__ float xs[E * 32];   // [k][r], 48 KB
    const int dir = blockIdx.y;
    const int t0  = blockIdx.x * 32;
    const int tid = threadIdx.x;
    const float* w   = dir ? w_b : w_f;
    const float* bb1 = dir ? b1b : b1f;
    const float* bb2 = dir ? b2b : b2f;

    #pragma unroll 1
    for (int i = 0; i < 48; i++) {
        int f = tid + i * 256;
        int r = f & 31, k = f >> 5;
        int tok = __ldg(sent + t0 + r);
        xs[k * 32 + r] = __ldg(emb + (size_t)tok * E + k);
    }
    __syncthreads();

    #pragma unroll 1
    for (int ch = 0; ch < 3; ch++) {
        int g = ch * 256 + tid;
        const float4* wr4 = (const float4*)(w + (size_t)g * E);
        float acc[32];
        #pragma unroll
        for (int r = 0; r < 32; r++) acc[r] = 0.0f;

        #pragma unroll 2
        for (int k4 = 0; k4 < E / 4; k4++) {
            float4 wv = __ldg(wr4 + k4);
            #pragma unroll
            for (int s = 0; s < 4; s++) {
                float wvs = (s == 0) ? wv.x : (s == 1) ? wv.y : (s == 2) ? wv.z : wv.w;
                const float4* x4 = (const float4*)(xs + (k4 * 4 + s) * 32);
                #pragma unroll
                for (int q = 0; q < 8; q++) {
                    float4 xv = x4[q];            // broadcast across warp
                    acc[4*q+0] += xv.x * wvs;
                    acc[4*q+1] += xv.y * wvs;
                    acc[4*q+2] += xv.z * wvs;
                    acc[4*q+3] += xv.w * wvs;
                }
            }
        }
        float bias = __ldg(bb1 + g) + __ldg(bb2 + g);
        #pragma unroll
        for (int r = 0; r < 32; r++)
            d_gpre[dir][t0 + r][g] = acc[r] + bias;
    }
}

// =====================================================================
// Kernel 2: LSTM scans. 2 clusters of 8 CTAs, 192 threads/CTA.
// W_hh slice register-resident. Per-step sync: producers push h to every
// CTA via st.async.shared::cluster with mbarrier::complete_tx (data +
// signal in ONE instruction, tx counted at store delivery — no remote
// arrive RMW storm). Consumer arms its barrier with a SINGLE local
// arrive.expect_tx(768 B) per phase and parity-waits. No cluster barrier
// in the loop -> no per-step L1 flush.
// =====================================================================
__global__ void __cluster_dims__(CSZ, 1, 1) __launch_bounds__(192, 1)
lstm_kernel(const float* __restrict__ whf, const float* __restrict__ whb)
{
    __shared__ __align__(16) float hbuf[2][H];
    __shared__ float part[192];
    __shared__ __align__(8) unsigned long long mb[2];

    unsigned rank; asm("mov.u32 %0, %%cluster_ctarank;" : "=r"(rank));
    const int dir = blockIdx.x >> 3;
    const int tid = threadIdx.x;
    const int gl  = tid % 96;          // local gate
    const int kh  = tid / 96;          // k half (0/1)
    const int typ = gl / 24, idx = gl % 24;
    const int gg  = typ * 192 + (int)rank * 24 + idx;   // global gate row
    const float* wh = dir ? whb : whf;

    // resident recurrent weights: 48 packed f32x2 per thread
    unsigned long long wreg[48];
    const unsigned long long* wrow =
        (const unsigned long long*)(wh + (size_t)gg * H) + kh * 48;
    #pragma unroll
    for (int j = 0; j < 48; j++) wreg[j] = __ldg(wrow + j);

    for (int i = tid; i < 2 * H; i += 192) (&hbuf[0][0])[i] = 0.0f;
    const unsigned mbl = smem_u32(&mb[0]);
    if (tid == 0) {
        asm volatile("mbarrier.init.shared.b64 [%0], %1;" :: "r"(mbl),     "r"(1) : "memory");
        asm volatile("mbarrier.init.shared.b64 [%0], %1;" :: "r"(mbl + 8), "r"(1) : "memory");
        // arm phase 0 of both barriers: 1 arrival + 192 floats of tx each
        asm volatile("mbarrier.arrive.expect_tx.shared.b64 _, [%0], %1;"
                     :: "r"(mbl),     "r"(H * 4) : "memory");
        asm volatile("mbarrier.arrive.expect_tx.shared.b64 _, [%0], %1;"
                     :: "r"(mbl + 8), "r"(H * 4) : "memory");
    }
    float c = 0.0f;
    __syncthreads();
    // one cluster sync: all CTAs' armed mbarriers + zeroed hbufs visible
    asm volatile("barrier.cluster.arrive.aligned;" ::: "memory");
    asm volatile("barrier.cluster.wait.aligned;"   ::: "memory");

    const float* gp = &d_gpre[dir][0][0];
    float* hout = &d_h[dir][0][0];
    const int hidx = (int)rank * 24 + (tid < 24 ? tid : 0);

    // hoisted remote addresses (producers only use them)
    unsigned ra_h[2][CSZ], ra_mb[2][CSZ];
    {
        unsigned lh0 = smem_u32(&hbuf[0][hidx]);
        unsigned lh1 = smem_u32(&hbuf[1][hidx]);
        #pragma unroll
        for (int r = 0; r < CSZ; r++) {
            asm("mapa.shared::cluster.u32 %0, %1, %2;" : "=r"(ra_h[0][r]) : "r"(lh0), "r"(r));
            asm("mapa.shared::cluster.u32 %0, %1, %2;" : "=r"(ra_h[1][r]) : "r"(lh1), "r"(r));
            asm("mapa.shared::cluster.u32 %0, %1, %2;" : "=r"(ra_mb[0][r]) : "r"(mbl), "r"(r));
            asm("mapa.shared::cluster.u32 %0, %1, %2;" : "=r"(ra_mb[1][r]) : "r"(mbl + 8), "r"(r));
        }
    }
    unsigned ph0 = 0, ph1 = 0;

    #pragma unroll 1
    for (int t = 0; t < SEQ; t++) {
        const int s = dir ? (SEQ - 1 - t) : t;
        const int b = t & 1;

        // prefetch this step's input-projected gates (overlaps the wait)
        float gp0 = 0.f, gp1 = 0.f, gp2 = 0.f, gp3 = 0.f;
        if (tid < 24) {
            const float* gpt = gp + (size_t)s * G4 + rank * 24 + tid;
            gp0 = __ldg(gpt);
            gp1 = __ldg(gpt + 192);
            gp2 = __ldg(gpt + 384);
            gp3 = __ldg(gpt + 576);
        }

        if (t > 0) {
            if (b) { mbar_wait_cluster(mbl + 8, ph1); ph1 ^= 1; }
            else   { mbar_wait_cluster(mbl,     ph0); ph0 ^= 1; }
            // re-arm this barrier for its next phase (single local arrive;
            // earliest conflicting tx is a full step away)
            if (tid == 0)
                asm volatile("mbarrier.arrive.expect_tx.shared.b64 _, [%0], %1;"
                             :: "r"(mbl + b * 8), "r"(H * 4) : "memory");
        }

        // 96-MAC half-dot: LDS.128 h (warp-broadcast), f32x2 FMA, 2 accs
        const ulonglong2* h2 =
            (const ulonglong2*)((const char*)hbuf + b * (H * 4)) + kh * 24;
        unsigned long long acc0 = 0ull, acc1 = 0ull;
        #pragma unroll
        for (int j = 0; j < 24; j++) {
            ulonglong2 hv = h2[j];
            asm("fma.rn.f32x2 %0, %1, %2, %0;" : "+l"(acc0) : "l"(hv.x), "l"(wreg[2*j]));
            asm("fma.rn.f32x2 %0, %1, %2, %0;" : "+l"(acc1) : "l"(hv.y), "l"(wreg[2*j+1]));
        }
        float a0x, a0y, a1x, a1y;
        asm("mov.b64 {%0,%1}, %2;" : "=f"(a0x), "=f"(a0y) : "l"(acc0));
        asm("mov.b64 {%0,%1}, %2;" : "=f"(a1x), "=f"(a1y) : "l"(acc1));
        part[tid] = (a0x + a0y) + (a1x + a1y);
        __syncthreads();

        if (tid < 24) {
            float gi = part[tid]      + part[tid + 96]  + gp0;
            float gf = part[tid + 24] + part[tid + 120] + gp1;
            float gz = part[tid + 48] + part[tid + 144] + gp2;
            float go = part[tid + 72] + part[tid + 168] + gp3;
            float iv = sigmoidf_(gi);
            float fv = sigmoidf_(gf);
            float gv = tanhf_(gz);
            float ov = sigmoidf_(go);
            c = fv * c + iv * gv;
            float hv = ov * tanhf_(c);
            hout[(size_t)s * H + hidx] = hv;

            // push h to every CTA's next-parity buffer: data + tx in one op
            unsigned hb = __float_as_uint(hv);
            const int tp = b ^ 1;
            #pragma unroll
            for (int r = 0; r < CSZ; r++)
                asm volatile(
                    "st.async.shared::cluster.mbarrier::complete_tx::bytes.b32 [%0], %1, [%2];"
                    :: "r"(ra_h[tp][r]), "r"(hb), "r"(ra_mb[tp][r]) : "memory");
        }
    }

    // keep smem alive until all peers' last DSMEM ops land
    asm volatile("barrier.cluster.arrive.aligned;" ::: "memory");
    asm volatile("barrier.cluster.wait.aligned;"   ::: "memory");
}

// =====================================================================
// Kernel 3: feats[t][tag] = concat(hf,hb)[t] . w_tag[tag] + b_tag
// =====================================================================
__global__ __launch_bounds__(352) void feats_kernel(
    const float* __restrict__ wtag, const float* __restrict__ btag)
{
    __shared__ float ws[T * 2 * H];
    __shared__ float bs[T];
    const int tid = threadIdx.x;
    for (int i = tid; i < T * 2 * H; i += 352) ws[i] = __ldg(wtag + i);
    if (tid < T) bs[tid] = __ldg(btag + tid);
    __syncthreads();

    const int tl = tid / T, tag = tid % T;
    const int t = blockIdx.x * 32 + tl;
    float acc = bs[tag];
    const float* wr = ws + tag * (2 * H);
    #pragma unroll 4
    for (int k = 0; k < H; k++) acc += __ldg(&d_h[0][t][k]) * wr[k];
    #pragma unroll 4
    for (int k = 0; k < H; k++) acc += __ldg(&d_h[1][t][k]) * wr[H + k];
    d_feats[t][tag] = acc;
}

// =====================================================================
// Kernel 4: Viterbi. 1 warp. Packed u64 max-tree, distance-2 feat
// prefetch, nibble-packed backpointers in 48 KB smem.
// =====================================================================
__global__ __launch_bounds__(32) void viterbi_kernel(
    const float* __restrict__ trans, float* __restrict__ out, int out_n)
{
    __shared__ unsigned char bsm[SEQ * 6];   // 49152 B
    const int lane = threadIdx.x;
    const int li = (lane < T) ? lane : 0;

    float tr[T];
    #pragma unroll
    for (int j = 0; j < T; j++) tr[j] = __ldg(trans + li * T + j);
    const float trStop = __ldg(trans + STOPTAG * T + li);

    float v = (lane == STARTTAG) ? 0.0f : NEGV;
    float fv0 = __ldg(&d_feats[0][li]);
    float fv1 = __ldg(&d_feats[1][li]);

    #pragma unroll 1
    for (int t = 0; t < SEQ; t++) {
        unsigned long long pk[T];
        #pragma unroll
        for (int j = 0; j < T; j++) {
            float vj = __shfl_sync(0xffffffffu, v, j);
            float sv = vj + tr[j];
            unsigned u = __float_as_uint(sv);
            unsigned key = u ^ ((((unsigned)((int)u >> 31)) >> 1) | 0x80000000u);
            pk[j] = ((unsigned long long)key << 4) | (unsigned)(10 - j);
        }
        unsigned long long a0 = mx64(pk[0], pk[1]);
        unsigned long long a1 = mx64(pk[2], pk[3]);
        unsigned long long a2 = mx64(pk[4], pk[5]);
        unsigned long long a3 = mx64(pk[6], pk[7]);
        unsigned long long a4 = mx64(pk[8], pk[9]);
        unsigned long long b0 = mx64(a0, a1);
        unsigned long long b1 = mx64(a2, a3);
        unsigned long long b2 = mx64(a4, pk[10]);
        unsigned long long best = mx64(mx64(b0, b1), b2);

        int bp = 10 - (int)(best & 15ull);
        unsigned key = (unsigned)(best >> 4);
        unsigned um = key ^ (((~((unsigned)((int)key >> 31))) >> 1) | 0x80000000u);
        float m = __uint_as_float(um);
        v = m + fv0;
        fv0 = fv1;
        int tn = t + 2 < SEQ ? t + 2 : SEQ - 1;
        fv1 = __ldg(&d_feats[tn][li]);

        int pb = __shfl_down_sync(0xffffffffu, bp, 1);
        if (lane < T && !(lane & 1)) {
            unsigned byte = (unsigned)bp | ((lane == 10 ? 0u : (unsigned)pb) << 4);
            bsm[t * 6 + (lane >> 1)] = (unsigned char)byte;
        }
    }

    float term = (lane < T) ? (v + trStop) : -3.4e38f;
    int bidx = lane;
    #pragma unroll
    for (int off = 16; off > 0; off >>= 1) {
        float ov = __shfl_down_sync(0xffffffffu, term, off);
        int   oi = __shfl_down_sync(0xffffffffu, bidx, off);
        if (ov > term || (ov == term && oi < bidx)) { term = ov; bidx = oi; }
    }
    if (lane == 0) {
        if (out_n > 0) out[0] = term;
        int cur = bidx;
        for (int t = SEQ - 1; t >= 0; t--) {
            if (1 + t < out_n) out[1 + t] = (float)cur;
            unsigned char byte = bsm[t * 6 + (cur >> 1)];
            cur = (cur & 1) ? (byte >> 4) : (byte & 15);
        }
    }
}

// =====================================================================
extern "C" void kernel_launch(void* const* d_in, const int* in_sizes, int n_in,
                              void* d_out, int out_size)
{
    const int*   sent   = (const int*)  d_in[0];
    const float* emb    = (const float*)d_in[1];
    const float* w_ih_f = (const float*)d_in[2];
    const float* w_hh_f = (const float*)d_in[3];
    const float* b_ih_f = (const float*)d_in[4];
    const float* b_hh_f = (const float*)d_in[5];
    const float* w_ih_b = (const float*)d_in[6];
    const float* w_hh_b = (const float*)d_in[7];
    const float* b_ih_b = (const float*)d_in[8];
    const float* b_hh_b = (const float*)d_in[9];
    const float* w_tag  = (const float*)d_in[10];
    const float* b_tag  = (const float*)d_in[11];
    const float* trans  = (const float*)d_in[12];
    float* out = (float*)d_out;

    gemm_in_kernel<<<dim3(SEQ / 32, 2), 256>>>(sent, emb,
        w_ih_f, b_ih_f, b_hh_f, w_ih_b, b_ih_b, b_hh_b);
    lstm_kernel<<<2 * CSZ, 192>>>(w_hh_f, w_hh_b);
    feats_kernel<<<SEQ / 32, 352>>>(w_tag, b_tag);
    viterbi_kernel<<<1, 32>>>(trans, out, out_size);
}